// round 1
// baseline (speedup 1.0000x reference)
#include <cuda_runtime.h>

// Problem constants
#define GM 8192            // B*S rows
#define GN 1024            // embed dim
#define GK 1024            // embed dim
#define SEQ 2048
#define NHEAD 16
#define HDIM 64
#define BATCH 4

// Scratch (allocation-free rule: __device__ globals)
__device__ float g_Q[(size_t)GM * GN];
__device__ float g_K[(size_t)GM * GN];
__device__ float g_V[(size_t)GM * GN];
__device__ float g_C[(size_t)GM * GN];

// ---------------------------------------------------------------------------
// C[m][n] = sum_k A[m][k] * W[n][k] + bias[n]   (A:[GM,GK], W:[GN,GK] row-major)
// BM=BN=128, BK=16, 256 threads, 8x8 per thread (interleaved mapping).
// ---------------------------------------------------------------------------
__global__ __launch_bounds__(256, 2)
void gemm_bias_kernel(const float* __restrict__ A, const float* __restrict__ W,
                      const float* __restrict__ bias, float* __restrict__ C)
{
    __shared__ float As[16][128];   // transposed: As[k][m]
    __shared__ float Bs[16][128];   // transposed: Bs[k][n]

    const int t  = threadIdx.x;
    const int tx = t & 15;
    const int ty = t >> 4;
    const int row0 = blockIdx.y * 128;
    const int col0 = blockIdx.x * 128;

    const int lr = t >> 2;          // 0..63
    const int lc = (t & 3) << 2;    // 0,4,8,12

    float acc[8][8];
#pragma unroll
    for (int i = 0; i < 8; i++)
#pragma unroll
        for (int j = 0; j < 8; j++) acc[i][j] = 0.f;

    for (int k0 = 0; k0 < GK; k0 += 16) {
#pragma unroll
        for (int rr = 0; rr < 2; rr++) {
            const int r = lr + rr * 64;
            float4 a = *(const float4*)(A + (size_t)(row0 + r) * GK + k0 + lc);
            As[lc + 0][r] = a.x; As[lc + 1][r] = a.y;
            As[lc + 2][r] = a.z; As[lc + 3][r] = a.w;
            float4 w = *(const float4*)(W + (size_t)(col0 + r) * GK + k0 + lc);
            Bs[lc + 0][r] = w.x; Bs[lc + 1][r] = w.y;
            Bs[lc + 2][r] = w.z; Bs[lc + 3][r] = w.w;
        }
        __syncthreads();
#pragma unroll
        for (int kk = 0; kk < 16; kk++) {
            float ra[8], rb[8];
#pragma unroll
            for (int i = 0; i < 8; i++) ra[i] = As[kk][ty + 16 * i];
#pragma unroll
            for (int j = 0; j < 8; j++) rb[j] = Bs[kk][tx + 16 * j];
#pragma unroll
            for (int i = 0; i < 8; i++)
#pragma unroll
                for (int j = 0; j < 8; j++)
                    acc[i][j] = fmaf(ra[i], rb[j], acc[i][j]);
        }
        __syncthreads();
    }

    float bj[8];
#pragma unroll
    for (int j = 0; j < 8; j++) bj[j] = bias[col0 + tx + 16 * j];
#pragma unroll
    for (int i = 0; i < 8; i++) {
        const size_t rbase = (size_t)(row0 + ty + 16 * i) * GN + col0;
#pragma unroll
        for (int j = 0; j < 8; j++)
            C[rbase + tx + 16 * j] = acc[i][j] + bj[j];
    }
}

// ---------------------------------------------------------------------------
// Flash attention: one CTA per (b, h, 64-query tile).
// Q/K/V/O in [B, S, D] layout with head slice at column h*64.
// 256 threads: thread (ty = t/16, tx = t%16) owns query rows {ty+16i},
// score cols / output dims {tx+16j}. Online softmax across 64-key tiles.
// ---------------------------------------------------------------------------
__global__ __launch_bounds__(256, 2)
void attn_kernel(const float* __restrict__ Q, const float* __restrict__ K,
                 const float* __restrict__ V, float* __restrict__ O)
{
    extern __shared__ float sm[];
    float* Qs = sm;                    // [64][64]
    float* Ks = sm + 64 * 64;          // [64][65] (pad -> conflict-free)
    float* Vs = Ks + 64 * 65;          // [64][65]
    float* Ps = Vs + 64 * 65;          // [64][65]

    const int t  = threadIdx.x;
    const int tx = t & 15;
    const int ty = t >> 4;
    const int q0 = blockIdx.x * 64;
    const int h  = blockIdx.y;
    const int b  = blockIdx.z;

    const size_t base = (size_t)b * SEQ * GN + (size_t)h * HDIM;

    const int lr = t >> 4;             // 0..15
    const int lc = (t & 15) << 2;      // 0..60 step 4

    // Load Q tile (float4, coalesced)
#pragma unroll
    for (int rr = 0; rr < 4; rr++) {
        const int r = lr + rr * 16;
        float4 q = *(const float4*)(Q + base + (size_t)(q0 + r) * GN + lc);
        *(float4*)(Qs + r * 64 + lc) = q;
    }

    float m_i[4], l_i[4], acc[4][4];
#pragma unroll
    for (int i = 0; i < 4; i++) {
        m_i[i] = -3.0e38f;
        l_i[i] = 0.f;
#pragma unroll
        for (int j = 0; j < 4; j++) acc[i][j] = 0.f;
    }

    for (int kt = 0; kt < SEQ / 64; kt++) {
        __syncthreads();   // previous PV done (and Qs visible on first iter)
#pragma unroll
        for (int rr = 0; rr < 4; rr++) {
            const int r = lr + rr * 16;
            float4 kv = *(const float4*)(K + base + (size_t)(kt * 64 + r) * GN + lc);
            Ks[r * 65 + lc + 0] = kv.x; Ks[r * 65 + lc + 1] = kv.y;
            Ks[r * 65 + lc + 2] = kv.z; Ks[r * 65 + lc + 3] = kv.w;
            float4 vv = *(const float4*)(V + base + (size_t)(kt * 64 + r) * GN + lc);
            Vs[r * 65 + lc + 0] = vv.x; Vs[r * 65 + lc + 1] = vv.y;
            Vs[r * 65 + lc + 2] = vv.z; Vs[r * 65 + lc + 3] = vv.w;
        }
        __syncthreads();

        // S = Q * K^T for this tile (4x4 per thread)
        float sc[4][4];
#pragma unroll
        for (int i = 0; i < 4; i++)
#pragma unroll
            for (int j = 0; j < 4; j++) sc[i][j] = 0.f;

        for (int d = 0; d < 64; d++) {
            float qv[4], kv[4];
#pragma unroll
            for (int i = 0; i < 4; i++) qv[i] = Qs[(ty + 16 * i) * 64 + d];
#pragma unroll
            for (int j = 0; j < 4; j++) kv[j] = Ks[(tx + 16 * j) * 65 + d];
#pragma unroll
            for (int i = 0; i < 4; i++)
#pragma unroll
                for (int j = 0; j < 4; j++)
                    sc[i][j] = fmaf(qv[i], kv[j], sc[i][j]);
        }

        const float scale = 0.125f;   // 1/sqrt(64)
#pragma unroll
        for (int i = 0; i < 4; i++) {
            float rmax = sc[i][0];
#pragma unroll
            for (int j = 1; j < 4; j++) rmax = fmaxf(rmax, sc[i][j]);
#pragma unroll
            for (int s = 8; s > 0; s >>= 1)
                rmax = fmaxf(rmax, __shfl_xor_sync(0xffffffffu, rmax, s));
            rmax *= scale;
            const float mnew  = fmaxf(m_i[i], rmax);
            const float alpha = __expf(m_i[i] - mnew);
            m_i[i] = mnew;

            float p[4];
            float rsum = 0.f;
#pragma unroll
            for (int j = 0; j < 4; j++) {
                p[j] = __expf(fmaf(sc[i][j], scale, -mnew));
                rsum += p[j];
            }
#pragma unroll
            for (int s = 8; s > 0; s >>= 1)
                rsum += __shfl_xor_sync(0xffffffffu, rsum, s);
            l_i[i] = l_i[i] * alpha + rsum;
#pragma unroll
            for (int j = 0; j < 4; j++) acc[i][j] *= alpha;
#pragma unroll
            for (int j = 0; j < 4; j++)
                Ps[(ty + 16 * i) * 65 + tx + 16 * j] = p[j];
        }
        __syncthreads();

        // O += P * V  (thread's 4 rows x 4 dims)
        for (int k = 0; k < 64; k++) {
            float pv[4], vv[4];
#pragma unroll
            for (int i = 0; i < 4; i++) pv[i] = Ps[(ty + 16 * i) * 65 + k];
#pragma unroll
            for (int j = 0; j < 4; j++) vv[j] = Vs[k * 65 + tx + 16 * j];
#pragma unroll
            for (int i = 0; i < 4; i++)
#pragma unroll
                for (int j = 0; j < 4; j++)
                    acc[i][j] = fmaf(pv[i], vv[j], acc[i][j]);
        }
    }

#pragma unroll
    for (int i = 0; i < 4; i++) {
        const float inv = 1.f / l_i[i];
        const size_t rbase = base + (size_t)(q0 + ty + 16 * i) * GN;
#pragma unroll
        for (int j = 0; j < 4; j++)
            O[rbase + tx + 16 * j] = acc[i][j] * inv;
    }
}

// ---------------------------------------------------------------------------
extern "C" void kernel_launch(void* const* d_in, const int* in_sizes, int n_in,
                              void* d_out, int out_size)
{
    const float* x  = (const float*)d_in[0];
    const float* Wq = (const float*)d_in[1];
    const float* bq = (const float*)d_in[2];
    const float* Wk = (const float*)d_in[3];
    const float* bk = (const float*)d_in[4];
    const float* Wv = (const float*)d_in[5];
    const float* bv = (const float*)d_in[6];
    const float* Wo = (const float*)d_in[7];
    const float* bo = (const float*)d_in[8];
    float* out = (float*)d_out;

    float *qb, *kb, *vb, *cb;
    cudaGetSymbolAddress((void**)&qb, g_Q);
    cudaGetSymbolAddress((void**)&kb, g_K);
    cudaGetSymbolAddress((void**)&vb, g_V);
    cudaGetSymbolAddress((void**)&cb, g_C);

    dim3 ggrid(GN / 128, GM / 128);

    gemm_bias_kernel<<<ggrid, 256>>>(x, Wq, bq, qb);
    gemm_bias_kernel<<<ggrid, 256>>>(x, Wk, bk, kb);
    gemm_bias_kernel<<<ggrid, 256>>>(x, Wv, bv, vb);

    const int smem = (64 * 64 + 3 * 64 * 65) * (int)sizeof(float);  // 66304 B
    cudaFuncSetAttribute(attn_kernel,
                         cudaFuncAttributeMaxDynamicSharedMemorySize, smem);
    dim3 agrid(SEQ / 64, NHEAD, BATCH);
    attn_kernel<<<agrid, 256, smem>>>(qb, kb, vb, cb);

    gemm_bias_kernel<<<ggrid, 256>>>(cb, Wo, bo, out);
}

// round 2
// speedup vs baseline: 3.0089x; 3.0089x over previous
#include <cuda_runtime.h>
#include <cstdint>

// Problem constants
#define GM 8192            // B*S rows
#define GN 1024            // embed dim
#define GK 1024            // embed dim
#define SEQ 2048
#define NHEAD 16
#define HDIM 64
#define BATCH 4

// Scratch (allocation-free rule: __device__ globals)
__device__ float g_Q[(size_t)GM * GN];
__device__ float g_K[(size_t)GM * GN];
__device__ float g_V[(size_t)GM * GN];
__device__ float g_C[(size_t)GM * GN];

// ---------------------------------------------------------------------------
// tf32 helpers
// ---------------------------------------------------------------------------
__device__ __forceinline__ float f2tf(float x) {
    uint32_t u;
    asm("cvt.rna.tf32.f32 %0, %1;" : "=r"(u) : "f"(x));
    return __uint_as_float(u);
}

__device__ __forceinline__ void mma_tf32(float* c, const uint32_t* a,
                                         uint32_t b0, uint32_t b1) {
    asm volatile(
        "mma.sync.aligned.m16n8k8.row.col.f32.tf32.tf32.f32 "
        "{%0,%1,%2,%3}, {%4,%5,%6,%7}, {%8,%9}, {%0,%1,%2,%3};"
        : "+f"(c[0]), "+f"(c[1]), "+f"(c[2]), "+f"(c[3])
        : "r"(a[0]), "r"(a[1]), "r"(a[2]), "r"(a[3]), "r"(b0), "r"(b1));
}

// ---------------------------------------------------------------------------
// C[m][n] = sum_k A[m][k] * W[n][k] + bias[n]
// BM=BN=128, BK=16, 256 threads, 8 warps in 2(M)x4(N), warp tile 64x32.
// Smem layout [k][m] stride 136 -> conflict-free fragment LDS.
// ---------------------------------------------------------------------------
#define SAS 136

__global__ __launch_bounds__(256)
void gemm_tf32_kernel(const float* __restrict__ A, const float* __restrict__ W,
                      const float* __restrict__ bias, float* __restrict__ C)
{
    __shared__ float As[16][SAS];
    __shared__ float Bs[16][SAS];

    const int t    = threadIdx.x;
    const int lane = t & 31;
    const int warp = t >> 5;
    const int g    = lane >> 2;   // 0..7
    const int t4   = lane & 3;    // 0..3
    const int wm   = (warp >> 2) * 64;   // 0,64
    const int wn   = (warp & 3) * 32;    // 0,32,64,96
    const int row0 = blockIdx.y * 128;
    const int col0 = blockIdx.x * 128;

    const int lr = t >> 2;          // 0..63
    const int lc = (t & 3) << 2;    // 0,4,8,12

    float c[4][4][4];
#pragma unroll
    for (int mi = 0; mi < 4; mi++)
#pragma unroll
        for (int ni = 0; ni < 4; ni++)
#pragma unroll
            for (int r = 0; r < 4; r++) c[mi][ni][r] = 0.f;

    for (int k0 = 0; k0 < GK; k0 += 16) {
#pragma unroll
        for (int rr = 0; rr < 2; rr++) {
            const int r = lr + rr * 64;
            float4 a = *(const float4*)(A + (size_t)(row0 + r) * GK + k0 + lc);
            As[lc + 0][r] = f2tf(a.x); As[lc + 1][r] = f2tf(a.y);
            As[lc + 2][r] = f2tf(a.z); As[lc + 3][r] = f2tf(a.w);
            float4 w = *(const float4*)(W + (size_t)(col0 + r) * GK + k0 + lc);
            Bs[lc + 0][r] = f2tf(w.x); Bs[lc + 1][r] = f2tf(w.y);
            Bs[lc + 2][r] = f2tf(w.z); Bs[lc + 3][r] = f2tf(w.w);
        }
        __syncthreads();

#pragma unroll
        for (int ks = 0; ks < 2; ks++) {
            const int kb = ks * 8;
            uint32_t af[4][4];
            uint32_t bf[4][2];
#pragma unroll
            for (int mi = 0; mi < 4; mi++) {
                const int m = wm + mi * 16 + g;
                af[mi][0] = __float_as_uint(As[kb + t4][m]);
                af[mi][1] = __float_as_uint(As[kb + t4][m + 8]);
                af[mi][2] = __float_as_uint(As[kb + t4 + 4][m]);
                af[mi][3] = __float_as_uint(As[kb + t4 + 4][m + 8]);
            }
#pragma unroll
            for (int ni = 0; ni < 4; ni++) {
                const int n = wn + ni * 8 + g;
                bf[ni][0] = __float_as_uint(Bs[kb + t4][n]);
                bf[ni][1] = __float_as_uint(Bs[kb + t4 + 4][n]);
            }
#pragma unroll
            for (int mi = 0; mi < 4; mi++)
#pragma unroll
                for (int ni = 0; ni < 4; ni++)
                    mma_tf32(c[mi][ni], af[mi], bf[ni][0], bf[ni][1]);
        }
        __syncthreads();
    }

#pragma unroll
    for (int mi = 0; mi < 4; mi++) {
        const int row = row0 + wm + mi * 16 + g;
#pragma unroll
        for (int ni = 0; ni < 4; ni++) {
            const int col = col0 + wn + ni * 8 + 2 * t4;
            const float b0 = bias[col], b1 = bias[col + 1];
            float2 v0 = make_float2(c[mi][ni][0] + b0, c[mi][ni][1] + b1);
            *(float2*)(C + (size_t)row * GN + col) = v0;
            float2 v1 = make_float2(c[mi][ni][2] + b0, c[mi][ni][3] + b1);
            *(float2*)(C + (size_t)(row + 8) * GN + col) = v1;
        }
    }
}

// ---------------------------------------------------------------------------
// Flash attention, tf32 mma. CTA = 64 queries x one (b,h). 128 threads.
// Warp w owns query rows [w*16, w*16+16). 64-key tiles, online softmax on
// C-fragment layout. P round-trips through smem (intra-warp only).
// ---------------------------------------------------------------------------
#define QS_LD 68
#define KS_LD 68
#define VS_LD 72
#define PS_LD 68

__global__ __launch_bounds__(128)
void attn_tf32_kernel(const float* __restrict__ Q, const float* __restrict__ K,
                      const float* __restrict__ V, float* __restrict__ O)
{
    extern __shared__ float sm[];
    float* Qs = sm;                        // [64][68]
    float* Ks = Qs + 64 * QS_LD;           // [64][68]
    float* Vs = Ks + 64 * KS_LD;           // [64][72]
    float* Ps = Vs + 64 * VS_LD;           // [64][68]

    const int t    = threadIdx.x;
    const int lane = t & 31;
    const int warp = t >> 5;
    const int g    = lane >> 2;
    const int t4   = lane & 3;
    const int q0   = blockIdx.x * 64;
    const size_t base = (size_t)blockIdx.z * SEQ * GN + (size_t)blockIdx.y * HDIM;

    const int ldr = t >> 4;            // 0..7
    const int ldc = (t & 15) << 2;     // 0..60

    // Load Q tile (tf32-converted at store)
#pragma unroll
    for (int rr = 0; rr < 8; rr++) {
        const int r = ldr + rr * 8;
        float4 q = *(const float4*)(Q + base + (size_t)(q0 + r) * GN + ldc);
        float* d = Qs + r * QS_LD + ldc;
        d[0] = f2tf(q.x); d[1] = f2tf(q.y); d[2] = f2tf(q.z); d[3] = f2tf(q.w);
    }
    __syncthreads();

    // Hoist Q fragments (constant across key tiles)
    const int mrow = warp * 16 + g;
    uint32_t qa[8][4];
#pragma unroll
    for (int kf = 0; kf < 8; kf++) {
        const float* qp = Qs + mrow * QS_LD + kf * 8 + t4;
        qa[kf][0] = __float_as_uint(qp[0]);
        qa[kf][1] = __float_as_uint(qp[8 * QS_LD]);
        qa[kf][2] = __float_as_uint(qp[4]);
        qa[kf][3] = __float_as_uint(qp[8 * QS_LD + 4]);
    }

    float m0 = -1e30f, m1 = -1e30f, l0 = 0.f, l1 = 0.f;
    float o[8][4];
#pragma unroll
    for (int nf = 0; nf < 8; nf++)
#pragma unroll
        for (int r = 0; r < 4; r++) o[nf][r] = 0.f;

    for (int kt = 0; kt < SEQ / 64; kt++) {
        __syncthreads();   // previous tile's Vs/Ps reads done
#pragma unroll
        for (int rr = 0; rr < 8; rr++) {
            const int r = ldr + rr * 8;
            float4 kv = *(const float4*)(K + base + (size_t)(kt * 64 + r) * GN + ldc);
            float* kd = Ks + r * KS_LD + ldc;
            kd[0] = f2tf(kv.x); kd[1] = f2tf(kv.y);
            kd[2] = f2tf(kv.z); kd[3] = f2tf(kv.w);
            float4 vv = *(const float4*)(V + base + (size_t)(kt * 64 + r) * GN + ldc);
            float* vd = Vs + r * VS_LD + ldc;
            vd[0] = f2tf(vv.x); vd[1] = f2tf(vv.y);
            vd[2] = f2tf(vv.z); vd[3] = f2tf(vv.w);
        }
        __syncthreads();

        // S = Q K^T  (raw, scale folded into exp)
        float s[8][4];
#pragma unroll
        for (int nf = 0; nf < 8; nf++)
#pragma unroll
            for (int r = 0; r < 4; r++) s[nf][r] = 0.f;

#pragma unroll
        for (int kf = 0; kf < 8; kf++) {
#pragma unroll
            for (int nf = 0; nf < 8; nf++) {
                const float* kp = Ks + (nf * 8 + g) * KS_LD + kf * 8 + t4;
                mma_tf32(s[nf], qa[kf],
                         __float_as_uint(kp[0]), __float_as_uint(kp[4]));
            }
        }

        // Online softmax (rows mrow, mrow+8; each owned by 4 lanes)
        float rmax0 = -1e30f, rmax1 = -1e30f;
#pragma unroll
        for (int nf = 0; nf < 8; nf++) {
            rmax0 = fmaxf(rmax0, fmaxf(s[nf][0], s[nf][1]));
            rmax1 = fmaxf(rmax1, fmaxf(s[nf][2], s[nf][3]));
        }
        rmax0 = fmaxf(rmax0, __shfl_xor_sync(0xffffffffu, rmax0, 1));
        rmax0 = fmaxf(rmax0, __shfl_xor_sync(0xffffffffu, rmax0, 2));
        rmax1 = fmaxf(rmax1, __shfl_xor_sync(0xffffffffu, rmax1, 1));
        rmax1 = fmaxf(rmax1, __shfl_xor_sync(0xffffffffu, rmax1, 2));

        const float mn0 = fmaxf(m0, rmax0);
        const float mn1 = fmaxf(m1, rmax1);
        const float alpha0 = __expf((m0 - mn0) * 0.125f);
        const float alpha1 = __expf((m1 - mn1) * 0.125f);
        m0 = mn0; m1 = mn1;

        float rs0 = 0.f, rs1 = 0.f;
#pragma unroll
        for (int nf = 0; nf < 8; nf++) {
            const float p0 = __expf((s[nf][0] - mn0) * 0.125f);
            const float p1 = __expf((s[nf][1] - mn0) * 0.125f);
            const float p2 = __expf((s[nf][2] - mn1) * 0.125f);
            const float p3 = __expf((s[nf][3] - mn1) * 0.125f);
            rs0 += p0 + p1;
            rs1 += p2 + p3;
            float* pp = Ps + mrow * PS_LD + nf * 8 + 2 * t4;
            pp[0] = f2tf(p0); pp[1] = f2tf(p1);
            pp[8 * PS_LD] = f2tf(p2); pp[8 * PS_LD + 1] = f2tf(p3);
        }
        rs0 += __shfl_xor_sync(0xffffffffu, rs0, 1);
        rs0 += __shfl_xor_sync(0xffffffffu, rs0, 2);
        rs1 += __shfl_xor_sync(0xffffffffu, rs1, 1);
        rs1 += __shfl_xor_sync(0xffffffffu, rs1, 2);
        l0 = l0 * alpha0 + rs0;
        l1 = l1 * alpha1 + rs1;

#pragma unroll
        for (int nf = 0; nf < 8; nf++) {
            o[nf][0] *= alpha0; o[nf][1] *= alpha0;
            o[nf][2] *= alpha1; o[nf][3] *= alpha1;
        }
        __syncwarp();   // P written in C-layout, read in A-layout: intra-warp

        // O += P V
#pragma unroll
        for (int kf = 0; kf < 8; kf++) {
            uint32_t pa[4];
            const float* pp = Ps + mrow * PS_LD + kf * 8 + t4;
            pa[0] = __float_as_uint(pp[0]);
            pa[1] = __float_as_uint(pp[8 * PS_LD]);
            pa[2] = __float_as_uint(pp[4]);
            pa[3] = __float_as_uint(pp[8 * PS_LD + 4]);
#pragma unroll
            for (int nf = 0; nf < 8; nf++) {
                const float* vp = Vs + (kf * 8 + t4) * VS_LD + nf * 8 + g;
                mma_tf32(o[nf], pa,
                         __float_as_uint(vp[0]),
                         __float_as_uint(vp[4 * VS_LD]));
            }
        }
    }

    const float inv0 = 1.f / l0;
    const float inv1 = 1.f / l1;
#pragma unroll
    for (int nf = 0; nf < 8; nf++) {
        const int col = nf * 8 + 2 * t4;
        float2 v0 = make_float2(o[nf][0] * inv0, o[nf][1] * inv0);
        *(float2*)(O + base + (size_t)(q0 + mrow) * GN + col) = v0;
        float2 v1 = make_float2(o[nf][2] * inv1, o[nf][3] * inv1);
        *(float2*)(O + base + (size_t)(q0 + mrow + 8) * GN + col) = v1;
    }
}

// ---------------------------------------------------------------------------
extern "C" void kernel_launch(void* const* d_in, const int* in_sizes, int n_in,
                              void* d_out, int out_size)
{
    const float* x  = (const float*)d_in[0];
    const float* Wq = (const float*)d_in[1];
    const float* bq = (const float*)d_in[2];
    const float* Wk = (const float*)d_in[3];
    const float* bk = (const float*)d_in[4];
    const float* Wv = (const float*)d_in[5];
    const float* bv = (const float*)d_in[6];
    const float* Wo = (const float*)d_in[7];
    const float* bo = (const float*)d_in[8];
    float* out = (float*)d_out;

    float *qb, *kb, *vb, *cb;
    cudaGetSymbolAddress((void**)&qb, g_Q);
    cudaGetSymbolAddress((void**)&kb, g_K);
    cudaGetSymbolAddress((void**)&vb, g_V);
    cudaGetSymbolAddress((void**)&cb, g_C);

    dim3 ggrid(GN / 128, GM / 128);

    gemm_tf32_kernel<<<ggrid, 256>>>(x, Wq, bq, qb);
    gemm_tf32_kernel<<<ggrid, 256>>>(x, Wk, bk, kb);
    gemm_tf32_kernel<<<ggrid, 256>>>(x, Wv, bv, vb);

    const int smem = (64 * (QS_LD + KS_LD + VS_LD + PS_LD)) * (int)sizeof(float);
    cudaFuncSetAttribute(attn_tf32_kernel,
                         cudaFuncAttributeMaxDynamicSharedMemorySize, smem);
    dim3 agrid(SEQ / 64, NHEAD, BATCH);
    attn_tf32_kernel<<<agrid, 128, smem>>>(qb, kb, vb, cb);

    gemm_tf32_kernel<<<ggrid, 256>>>(cb, Wo, bo, out);
}

// round 3
// speedup vs baseline: 6.3028x; 2.0947x over previous
#include <cuda_runtime.h>
#include <cuda_fp16.h>
#include <cstdint>

#define GM 8192
#define GN 1024
#define GK 1024
#define SEQ 2048
#define NHEAD 16
#define HDIM 64
#define BATCH 4

// fp16 staging buffers (allocation-free rule: __device__ globals)
__device__ __half g_Xh[(size_t)GM * GK];
__device__ __half g_Wqh[(size_t)GN * GK];
__device__ __half g_Wkh[(size_t)GN * GK];
__device__ __half g_Wvh[(size_t)GN * GK];
__device__ __half g_Woh[(size_t)GN * GK];
__device__ __half g_Qh[(size_t)GM * GN];
__device__ __half g_Kh[(size_t)GM * GN];
__device__ __half g_Vh[(size_t)GM * GN];
__device__ __half g_Ch[(size_t)GM * GN];

// ---------------------------------------------------------------------------
// PTX helpers
// ---------------------------------------------------------------------------
__device__ __forceinline__ uint32_t smem_u32(const void* p) {
    return (uint32_t)__cvta_generic_to_shared(p);
}
#define SWZ(o) ((o) ^ (((o) >> 3) & 0x70))

__device__ __forceinline__ void cp16(uint32_t dst, const void* src) {
    asm volatile("cp.async.cg.shared.global [%0], [%1], 16;" :: "r"(dst), "l"(src));
}
__device__ __forceinline__ void cp_commit() {
    asm volatile("cp.async.commit_group;");
}
template <int N>
__device__ __forceinline__ void cp_wait() {
    asm volatile("cp.async.wait_group %0;" :: "n"(N));
}

__device__ __forceinline__ void ldsm4(uint32_t& a, uint32_t& b, uint32_t& c,
                                      uint32_t& d, uint32_t addr) {
    asm volatile("ldmatrix.sync.aligned.m8n8.x4.shared.b16 {%0,%1,%2,%3}, [%4];"
                 : "=r"(a), "=r"(b), "=r"(c), "=r"(d) : "r"(addr));
}
__device__ __forceinline__ void ldsm4t(uint32_t& a, uint32_t& b, uint32_t& c,
                                       uint32_t& d, uint32_t addr) {
    asm volatile("ldmatrix.sync.aligned.m8n8.x4.trans.shared.b16 {%0,%1,%2,%3}, [%4];"
                 : "=r"(a), "=r"(b), "=r"(c), "=r"(d) : "r"(addr));
}

__device__ __forceinline__ void mma_h(float* c, const uint32_t* a,
                                      uint32_t b0, uint32_t b1) {
    asm volatile(
        "mma.sync.aligned.m16n8k16.row.col.f32.f16.f16.f32 "
        "{%0,%1,%2,%3}, {%4,%5,%6,%7}, {%8,%9}, {%0,%1,%2,%3};"
        : "+f"(c[0]), "+f"(c[1]), "+f"(c[2]), "+f"(c[3])
        : "r"(a[0]), "r"(a[1]), "r"(a[2]), "r"(a[3]), "r"(b0), "r"(b1));
}

__device__ __forceinline__ uint32_t packh2(float x, float y) {
    __half2 h = __floats2half2_rn(x, y);
    return *(uint32_t*)&h;
}

// ---------------------------------------------------------------------------
// fp32 -> fp16 rounding pre-pass
// ---------------------------------------------------------------------------
__global__ void f2h_kernel(const float* __restrict__ in, __half* __restrict__ out,
                           int n4) {
    int i = blockIdx.x * blockDim.x + threadIdx.x;
    if (i < n4) {
        float4 v = *(const float4*)(in + (size_t)i * 4);
        __half2* o = (__half2*)out + (size_t)i * 2;
        o[0] = __floats2half2_rn(v.x, v.y);
        o[1] = __floats2half2_rn(v.z, v.w);
    }
}

// ---------------------------------------------------------------------------
// GEMM: C[m][n] = A[m][:] . W[n][:] + bias[n]   (fp16 in, fp32 accum)
// BM=BN=128, BK=64, 256 threads, 8 warps 2(M)x4(N), warp 64x32.
// SW128 smem, 2-stage cp.async, ldmatrix fragments.
// ---------------------------------------------------------------------------
template <int OUT_HALF>
__global__ __launch_bounds__(256)
void gemm_h_kernel(const __half* __restrict__ A, const __half* __restrict__ B,
                   const float* __restrict__ bias, void* __restrict__ Cout)
{
    extern __shared__ char smraw[];
    const int t    = threadIdx.x;
    const int lane = t & 31;
    const int warp = t >> 5;
    const int g    = lane >> 2;
    const int t4   = lane & 3;
    const int wm   = (warp >> 2) * 64;
    const int wn   = (warp & 3) * 32;
    const int row0 = blockIdx.y * 128;
    const int col0 = blockIdx.x * 128;
    const uint32_t smb = smem_u32(smraw);
    // stage s: A at s*32768, B at s*32768 + 16384  (128 rows x 128B each)

    float acc[4][4][4];
#pragma unroll
    for (int mi = 0; mi < 4; mi++)
#pragma unroll
        for (int nf = 0; nf < 4; nf++)
#pragma unroll
            for (int r = 0; r < 4; r++) acc[mi][nf][r] = 0.f;

    const int lrow = t >> 3;     // 0..31 (of 128 rows, x4)
    const int lcb  = t & 7;      // 16B chunk 0..7

    auto load_stage = [&](int kt, int s) {
        const __half* Ag = A + (size_t)row0 * GK + kt * 64;
        const __half* Bg = B + (size_t)col0 * GK + kt * 64;
        const uint32_t as = smb + s * 32768;
        const uint32_t bs = as + 16384;
#pragma unroll
        for (int i = 0; i < 4; i++) {
            const int r = lrow + i * 32;
            const uint32_t off = SWZ(r * 128 + lcb * 16);
            cp16(as + off, Ag + (size_t)r * GK + lcb * 8);
            cp16(bs + off, Bg + (size_t)r * GK + lcb * 8);
        }
        cp_commit();
    };

    load_stage(0, 0);

    const int NT = GK / 64;
    for (int kt = 0; kt < NT; kt++) {
        if (kt + 1 < NT) { load_stage(kt + 1, (kt + 1) & 1); cp_wait<1>(); }
        else             { cp_wait<0>(); }
        __syncthreads();

        const uint32_t as = smb + (kt & 1) * 32768;
        const uint32_t bs = as + 16384;

#pragma unroll
        for (int ks = 0; ks < 4; ks++) {
            const int k0 = ks * 16;
            uint32_t af[4][4], bf[4][2];
#pragma unroll
            for (int mi = 0; mi < 4; mi++) {
                const int r  = wm + mi * 16 + (lane & 7) + ((lane >> 3) & 1) * 8;
                const int cb = k0 * 2 + ((lane >> 4) & 1) * 16;
                ldsm4(af[mi][0], af[mi][1], af[mi][2], af[mi][3],
                      as + SWZ(r * 128 + cb));
            }
#pragma unroll
            for (int np = 0; np < 2; np++) {
                const int r  = wn + np * 16 + (lane & 7) + ((lane >> 4) & 1) * 8;
                const int cb = k0 * 2 + ((lane >> 3) & 1) * 16;
                uint32_t b0, b1, b2, b3;
                ldsm4(b0, b1, b2, b3, bs + SWZ(r * 128 + cb));
                bf[np * 2][0] = b0; bf[np * 2][1] = b1;
                bf[np * 2 + 1][0] = b2; bf[np * 2 + 1][1] = b3;
            }
#pragma unroll
            for (int mi = 0; mi < 4; mi++)
#pragma unroll
                for (int nf = 0; nf < 4; nf++)
                    mma_h(acc[mi][nf], af[mi], bf[nf][0], bf[nf][1]);
        }
        __syncthreads();
    }

#pragma unroll
    for (int mi = 0; mi < 4; mi++) {
        const int row = row0 + wm + mi * 16 + g;
#pragma unroll
        for (int nf = 0; nf < 4; nf++) {
            const int col = col0 + wn + nf * 8 + 2 * t4;
            const float b0 = bias[col], b1 = bias[col + 1];
            const float v00 = acc[mi][nf][0] + b0, v01 = acc[mi][nf][1] + b1;
            const float v10 = acc[mi][nf][2] + b0, v11 = acc[mi][nf][3] + b1;
            if (OUT_HALF) {
                __half2* o = (__half2*)Cout;
                o[((size_t)row * GN + col) >> 1]       = __floats2half2_rn(v00, v01);
                o[((size_t)(row + 8) * GN + col) >> 1] = __floats2half2_rn(v10, v11);
            } else {
                float* o = (float*)Cout;
                *(float2*)(o + (size_t)row * GN + col)       = make_float2(v00, v01);
                *(float2*)(o + (size_t)(row + 8) * GN + col) = make_float2(v10, v11);
            }
        }
    }
}

// ---------------------------------------------------------------------------
// Flash attention, fp16 mma, register-resident P.
// CTA = 128 queries x one (b,h), 4 warps x 32 q. 64-key tiles,
// K/V double-buffered via cp.async. 128 threads.
// Smem: Q 16KB @0; stage s: K @16384+s*16384 (8KB), V = K+8192.
// ---------------------------------------------------------------------------
__global__ __launch_bounds__(128)
void attn_h_kernel(const __half* __restrict__ Q, const __half* __restrict__ K,
                   const __half* __restrict__ V, __half* __restrict__ O)
{
    extern __shared__ char smraw[];
    const int t    = threadIdx.x;
    const int lane = t & 31;
    const int warp = t >> 5;
    const int g    = lane >> 2;
    const int t4   = lane & 3;
    const int q0   = blockIdx.x * 128;
    const size_t base = (size_t)blockIdx.z * SEQ * GN + (size_t)blockIdx.y * HDIM;
    const uint32_t smb = smem_u32(smraw);

    const int lrow = t >> 3;     // 0..15
    const int lcb  = t & 7;

    // Q: 128 rows x 8 chunks = 1024 chunks, 8 per thread
    {
        const __half* Qg = Q + base + (size_t)q0 * GN;
#pragma unroll
        for (int i = 0; i < 8; i++) {
            const int r = lrow + i * 16;
            cp16(smb + SWZ(r * 128 + lcb * 16), Qg + (size_t)r * GN + lcb * 8);
        }
    }
    auto load_kv = [&](int kt, int s) {
        const __half* Kg = K + base + (size_t)(kt * 64) * GN;
        const __half* Vg = V + base + (size_t)(kt * 64) * GN;
        const uint32_t ks = smb + 16384 + s * 16384;
        const uint32_t vs = ks + 8192;
#pragma unroll
        for (int i = 0; i < 4; i++) {
            const int r = lrow + i * 16;
            const uint32_t off = SWZ(r * 128 + lcb * 16);
            cp16(ks + off, Kg + (size_t)r * GN + lcb * 8);
            cp16(vs + off, Vg + (size_t)r * GN + lcb * 8);
        }
    };

    load_kv(0, 0);
    cp_commit();                // group 0: Q + KV0
    load_kv(1, 1);
    cp_commit();                // group 1: KV1
    cp_wait<1>();
    __syncthreads();

    // Hoist Q fragments
    uint32_t qa[2][4][4];
#pragma unroll
    for (int mi = 0; mi < 2; mi++)
#pragma unroll
        for (int kf = 0; kf < 4; kf++) {
            const int r  = warp * 32 + mi * 16 + (lane & 7) + ((lane >> 3) & 1) * 8;
            const int cb = kf * 32 + ((lane >> 4) & 1) * 16;
            ldsm4(qa[mi][kf][0], qa[mi][kf][1], qa[mi][kf][2], qa[mi][kf][3],
                  smb + SWZ(r * 128 + cb));
        }

    float mrun[2][2], lrun[2][2];
    float o[2][8][4];
#pragma unroll
    for (int mi = 0; mi < 2; mi++) {
        mrun[mi][0] = mrun[mi][1] = -1e30f;
        lrun[mi][0] = lrun[mi][1] = 0.f;
#pragma unroll
        for (int nf = 0; nf < 8; nf++)
#pragma unroll
            for (int r = 0; r < 4; r++) o[mi][nf][r] = 0.f;
    }

    const float cexp = 0.125f * 1.44269504089f;   // log2(e)/sqrt(Hd)
    const int NT = SEQ / 64;

    for (int kt = 0; kt < NT; kt++) {
        const uint32_t ks = smb + 16384 + (kt & 1) * 16384;
        const uint32_t vs = ks + 8192;

        // S = Q K^T
        float s_[2][8][4];
#pragma unroll
        for (int mi = 0; mi < 2; mi++)
#pragma unroll
            for (int nf = 0; nf < 8; nf++)
#pragma unroll
                for (int r = 0; r < 4; r++) s_[mi][nf][r] = 0.f;

#pragma unroll
        for (int kf = 0; kf < 4; kf++) {
#pragma unroll
            for (int np = 0; np < 4; np++) {
                const int r  = np * 16 + (lane & 7) + ((lane >> 4) & 1) * 8;
                const int cb = kf * 32 + ((lane >> 3) & 1) * 16;
                uint32_t b0, b1, b2, b3;
                ldsm4(b0, b1, b2, b3, ks + SWZ(r * 128 + cb));
#pragma unroll
                for (int mi = 0; mi < 2; mi++) {
                    mma_h(s_[mi][np * 2],     qa[mi][kf], b0, b1);
                    mma_h(s_[mi][np * 2 + 1], qa[mi][kf], b2, b3);
                }
            }
        }

        // Online softmax + P in A-fragment registers
        uint32_t pa[2][4][4];
#pragma unroll
        for (int mi = 0; mi < 2; mi++) {
            float mx0 = -1e30f, mx1 = -1e30f;
#pragma unroll
            for (int nf = 0; nf < 8; nf++) {
                mx0 = fmaxf(mx0, fmaxf(s_[mi][nf][0], s_[mi][nf][1]));
                mx1 = fmaxf(mx1, fmaxf(s_[mi][nf][2], s_[mi][nf][3]));
            }
            mx0 = fmaxf(mx0, __shfl_xor_sync(0xffffffffu, mx0, 1));
            mx0 = fmaxf(mx0, __shfl_xor_sync(0xffffffffu, mx0, 2));
            mx1 = fmaxf(mx1, __shfl_xor_sync(0xffffffffu, mx1, 1));
            mx1 = fmaxf(mx1, __shfl_xor_sync(0xffffffffu, mx1, 2));

            const float mn0 = fmaxf(mrun[mi][0], mx0);
            const float mn1 = fmaxf(mrun[mi][1], mx1);
            const float a0  = exp2f((mrun[mi][0] - mn0) * cexp);
            const float a1  = exp2f((mrun[mi][1] - mn1) * cexp);
            mrun[mi][0] = mn0; mrun[mi][1] = mn1;

            float rs0 = 0.f, rs1 = 0.f;
#pragma unroll
            for (int nf = 0; nf < 8; nf++) {
                const float p0 = exp2f((s_[mi][nf][0] - mn0) * cexp);
                const float p1 = exp2f((s_[mi][nf][1] - mn0) * cexp);
                const float p2 = exp2f((s_[mi][nf][2] - mn1) * cexp);
                const float p3 = exp2f((s_[mi][nf][3] - mn1) * cexp);
                rs0 += p0 + p1;
                rs1 += p2 + p3;
                const int kf = nf >> 1, hf = (nf & 1) * 2;
                pa[mi][kf][hf]     = packh2(p0, p1);
                pa[mi][kf][hf + 1] = packh2(p2, p3);
            }
            rs0 += __shfl_xor_sync(0xffffffffu, rs0, 1);
            rs0 += __shfl_xor_sync(0xffffffffu, rs0, 2);
            rs1 += __shfl_xor_sync(0xffffffffu, rs1, 1);
            rs1 += __shfl_xor_sync(0xffffffffu, rs1, 2);
            lrun[mi][0] = lrun[mi][0] * a0 + rs0;
            lrun[mi][1] = lrun[mi][1] * a1 + rs1;
#pragma unroll
            for (int nf = 0; nf < 8; nf++) {
                o[mi][nf][0] *= a0; o[mi][nf][1] *= a0;
                o[mi][nf][2] *= a1; o[mi][nf][3] *= a1;
            }
        }

        // O += P V
#pragma unroll
        for (int kf = 0; kf < 4; kf++) {
#pragma unroll
            for (int np = 0; np < 4; np++) {
                const int r  = kf * 16 + (lane & 7) + ((lane >> 3) & 1) * 8;
                const int cb = np * 32 + ((lane >> 4) & 1) * 16;
                uint32_t b0, b1, b2, b3;
                ldsm4t(b0, b1, b2, b3, vs + SWZ(r * 128 + cb));
#pragma unroll
                for (int mi = 0; mi < 2; mi++) {
                    mma_h(o[mi][np * 2],     pa[mi][kf], b0, b1);
                    mma_h(o[mi][np * 2 + 1], pa[mi][kf], b2, b3);
                }
            }
        }

        __syncthreads();   // all warps done reading stage kt&1
        if (kt + 2 < NT) { load_kv(kt + 2, kt & 1); cp_commit(); }
        if (kt + 1 < NT) {
            if (kt + 2 < NT) cp_wait<1>(); else cp_wait<0>();
            __syncthreads();
        }
    }

    // Epilogue: O /= l, store fp16
#pragma unroll
    for (int mi = 0; mi < 2; mi++) {
        const float inv0 = 1.f / lrun[mi][0];
        const float inv1 = 1.f / lrun[mi][1];
        const int row = q0 + warp * 32 + mi * 16 + g;
#pragma unroll
        for (int nf = 0; nf < 8; nf++) {
            const int col = nf * 8 + 2 * t4;
            *(__half2*)(O + base + (size_t)row * GN + col) =
                __floats2half2_rn(o[mi][nf][0] * inv0, o[mi][nf][1] * inv0);
            *(__half2*)(O + base + (size_t)(row + 8) * GN + col) =
                __floats2half2_rn(o[mi][nf][2] * inv1, o[mi][nf][3] * inv1);
        }
    }
}

// ---------------------------------------------------------------------------
extern "C" void kernel_launch(void* const* d_in, const int* in_sizes, int n_in,
                              void* d_out, int out_size)
{
    const float* x  = (const float*)d_in[0];
    const float* Wq = (const float*)d_in[1];
    const float* bq = (const float*)d_in[2];
    const float* Wk = (const float*)d_in[3];
    const float* bk = (const float*)d_in[4];
    const float* Wv = (const float*)d_in[5];
    const float* bv = (const float*)d_in[6];
    const float* Wo = (const float*)d_in[7];
    const float* bo = (const float*)d_in[8];
    float* out = (float*)d_out;

    __half *xh, *wqh, *wkh, *wvh, *woh, *qh, *kh, *vh, *ch;
    cudaGetSymbolAddress((void**)&xh,  g_Xh);
    cudaGetSymbolAddress((void**)&wqh, g_Wqh);
    cudaGetSymbolAddress((void**)&wkh, g_Wkh);
    cudaGetSymbolAddress((void**)&wvh, g_Wvh);
    cudaGetSymbolAddress((void**)&woh, g_Woh);
    cudaGetSymbolAddress((void**)&qh,  g_Qh);
    cudaGetSymbolAddress((void**)&kh,  g_Kh);
    cudaGetSymbolAddress((void**)&vh,  g_Vh);
    cudaGetSymbolAddress((void**)&ch,  g_Ch);

    // fp16 pre-rounding
    {
        const int nx4 = GM * GK / 4;
        f2h_kernel<<<(nx4 + 255) / 256, 256>>>(x, xh, nx4);
        const int nw4 = GN * GK / 4;
        f2h_kernel<<<(nw4 + 255) / 256, 256>>>(Wq, wqh, nw4);
        f2h_kernel<<<(nw4 + 255) / 256, 256>>>(Wk, wkh, nw4);
        f2h_kernel<<<(nw4 + 255) / 256, 256>>>(Wv, wvh, nw4);
        f2h_kernel<<<(nw4 + 255) / 256, 256>>>(Wo, woh, nw4);
    }

    const int gsm = 65536;
    cudaFuncSetAttribute(gemm_h_kernel<1>,
                         cudaFuncAttributeMaxDynamicSharedMemorySize, gsm);
    cudaFuncSetAttribute(gemm_h_kernel<0>,
                         cudaFuncAttributeMaxDynamicSharedMemorySize, gsm);
    dim3 ggrid(GN / 128, GM / 128);

    gemm_h_kernel<1><<<ggrid, 256, gsm>>>(xh, wqh, bq, qh);
    gemm_h_kernel<1><<<ggrid, 256, gsm>>>(xh, wkh, bk, kh);
    gemm_h_kernel<1><<<ggrid, 256, gsm>>>(xh, wvh, bv, vh);

    const int asm_ = 49152;
    cudaFuncSetAttribute(attn_h_kernel,
                         cudaFuncAttributeMaxDynamicSharedMemorySize, asm_);
    dim3 agrid(SEQ / 128, NHEAD, BATCH);
    attn_h_kernel<<<agrid, 128, asm_>>>(qh, kh, vh, ch);

    gemm_h_kernel<0><<<ggrid, 256, gsm>>>(ch, woh, bo, out);
}

// round 6
// speedup vs baseline: 10.0955x; 1.6017x over previous
#include <cuda_runtime.h>
#include <cuda_fp16.h>
#include <cstdint>

#define GM 8192
#define GN 1024
#define GK 1024
#define SEQ 2048
#define NHEAD 16
#define HDIM 64
#define BATCH 4

// fp16 staging buffers (allocation-free rule: __device__ globals)
__device__ __half g_Xh[(size_t)GM * GK];
__device__ __half g_Wqh[(size_t)GN * GK];
__device__ __half g_Wkh[(size_t)GN * GK];
__device__ __half g_Wvh[(size_t)GN * GK];
__device__ __half g_Woh[(size_t)GN * GK];
__device__ __half g_Qh[(size_t)GM * GN];
__device__ __half g_Kh[(size_t)GM * GN];
__device__ __half g_Vh[(size_t)GM * GN];
__device__ __half g_Ch[(size_t)GM * GN];

// ---------------------------------------------------------------------------
// PTX helpers
// ---------------------------------------------------------------------------
__device__ __forceinline__ uint32_t smem_u32(const void* p) {
    return (uint32_t)__cvta_generic_to_shared(p);
}
#define SWZ(o) ((o) ^ (((o) >> 3) & 0x70))

__device__ __forceinline__ void cp16(uint32_t dst, const void* src) {
    asm volatile("cp.async.cg.shared.global [%0], [%1], 16;" :: "r"(dst), "l"(src));
}
__device__ __forceinline__ void cp_commit() {
    asm volatile("cp.async.commit_group;");
}
template <int N>
__device__ __forceinline__ void cp_wait() {
    asm volatile("cp.async.wait_group %0;" :: "n"(N));
}

__device__ __forceinline__ void ldsm4(uint32_t& a, uint32_t& b, uint32_t& c,
                                      uint32_t& d, uint32_t addr) {
    asm volatile("ldmatrix.sync.aligned.m8n8.x4.shared.b16 {%0,%1,%2,%3}, [%4];"
                 : "=r"(a), "=r"(b), "=r"(c), "=r"(d) : "r"(addr));
}
__device__ __forceinline__ void ldsm4t(uint32_t& a, uint32_t& b, uint32_t& c,
                                       uint32_t& d, uint32_t addr) {
    asm volatile("ldmatrix.sync.aligned.m8n8.x4.trans.shared.b16 {%0,%1,%2,%3}, [%4];"
                 : "=r"(a), "=r"(b), "=r"(c), "=r"(d) : "r"(addr));
}

__device__ __forceinline__ void mma_h(float* c, const uint32_t* a,
                                      uint32_t b0, uint32_t b1) {
    asm volatile(
        "mma.sync.aligned.m16n8k16.row.col.f32.f16.f16.f32 "
        "{%0,%1,%2,%3}, {%4,%5,%6,%7}, {%8,%9}, {%0,%1,%2,%3};"
        : "+f"(c[0]), "+f"(c[1]), "+f"(c[2]), "+f"(c[3])
        : "r"(a[0]), "r"(a[1]), "r"(a[2]), "r"(a[3]), "r"(b0), "r"(b1));
}

__device__ __forceinline__ uint32_t packh2(float x, float y) {
    __half2 h = __floats2half2_rn(x, y);
    return *(uint32_t*)&h;
}

// ---------------------------------------------------------------------------
// fp32 -> fp16 rounding pre-pass
// ---------------------------------------------------------------------------
__global__ void f2h_kernel(const float* __restrict__ in, __half* __restrict__ out,
                           int n4) {
    int i = blockIdx.x * blockDim.x + threadIdx.x;
    if (i < n4) {
        float4 v = *(const float4*)(in + (size_t)i * 4);
        __half2* o = (__half2*)out + (size_t)i * 2;
        o[0] = __floats2half2_rn(v.x, v.y);
        o[1] = __floats2half2_rn(v.z, v.w);
    }
}

// ---------------------------------------------------------------------------
// GEMM: C[m][n] = A[m][:] . W[n][:] + bias[n]   (fp16 in, fp32 accum)
// BM=BN=128, BK=64, 128 threads, 4 warps 2x2, warp tile 64x64.
// SW128 smem, 3-stage cp.async pipeline, ldmatrix fragments, 2 CTAs/SM.
// ---------------------------------------------------------------------------
#define STG_SZ 32768    // A 16KB + B 16KB per stage
#define NT_K 16         // 1024 / 64

template <int OUT_HALF>
__global__ __launch_bounds__(128, 2)
void gemm_h_kernel(const __half* __restrict__ A, const __half* __restrict__ B,
                   const float* __restrict__ bias, void* __restrict__ Cout)
{
    extern __shared__ char smraw[];
    const int t    = threadIdx.x;
    const int lane = t & 31;
    const int warp = t >> 5;
    const int g    = lane >> 2;
    const int t4   = lane & 3;
    const int wm   = (warp >> 1) * 64;
    const int wn   = (warp & 1) * 64;
    const int row0 = blockIdx.y * 128;
    const int col0 = blockIdx.x * 128;
    const uint32_t smb = smem_u32(smraw);

    float acc[4][8][4];
#pragma unroll
    for (int mi = 0; mi < 4; mi++)
#pragma unroll
        for (int nf = 0; nf < 8; nf++)
#pragma unroll
            for (int r = 0; r < 4; r++) acc[mi][nf][r] = 0.f;

    const int lrow = t >> 3;     // 0..15
    const int lcb  = t & 7;      // 16B chunk 0..7

    auto load_stage = [&](int kt, int s) {
        const __half* Ag = A + (size_t)row0 * GK + kt * 64;
        const __half* Bg = B + (size_t)col0 * GK + kt * 64;
        const uint32_t as = smb + s * STG_SZ;
        const uint32_t bs = as + 16384;
#pragma unroll
        for (int i = 0; i < 8; i++) {
            const int r = lrow + i * 16;
            const uint32_t off = SWZ(r * 128 + lcb * 16);
            cp16(as + off, Ag + (size_t)r * GK + lcb * 8);
            cp16(bs + off, Bg + (size_t)r * GK + lcb * 8);
        }
        cp_commit();
    };

    load_stage(0, 0);
    load_stage(1, 1);
    load_stage(2, 2);

#pragma unroll 1
    for (int kt = 0; kt < NT_K; kt++) {
        const int s = kt % 3;
        if (kt <= NT_K - 3)      cp_wait<2>();
        else if (kt == NT_K - 2) cp_wait<1>();
        else                     cp_wait<0>();
        __syncthreads();

        const uint32_t as = smb + s * STG_SZ;
        const uint32_t bs = as + 16384;

#pragma unroll
        for (int ks = 0; ks < 4; ks++) {
            const int k0 = ks * 16;
            uint32_t af[4][4], bf[8][2];
#pragma unroll
            for (int mi = 0; mi < 4; mi++) {
                const int r  = wm + mi * 16 + (lane & 7) + ((lane >> 3) & 1) * 8;
                const int cb = k0 * 2 + ((lane >> 4) & 1) * 16;
                ldsm4(af[mi][0], af[mi][1], af[mi][2], af[mi][3],
                      as + SWZ(r * 128 + cb));
            }
#pragma unroll
            for (int np = 0; np < 4; np++) {
                const int r  = wn + np * 16 + (lane & 7) + ((lane >> 4) & 1) * 8;
                const int cb = k0 * 2 + ((lane >> 3) & 1) * 16;
                uint32_t b0, b1, b2, b3;
                ldsm4(b0, b1, b2, b3, bs + SWZ(r * 128 + cb));
                bf[np * 2][0] = b0; bf[np * 2][1] = b1;
                bf[np * 2 + 1][0] = b2; bf[np * 2 + 1][1] = b3;
            }
#pragma unroll
            for (int mi = 0; mi < 4; mi++)
#pragma unroll
                for (int nf = 0; nf < 8; nf++)
                    mma_h(acc[mi][nf], af[mi], bf[nf][0], bf[nf][1]);
        }
        __syncthreads();
        if (kt + 3 < NT_K) load_stage(kt + 3, s);
    }

#pragma unroll
    for (int mi = 0; mi < 4; mi++) {
        const int row = row0 + wm + mi * 16 + g;
#pragma unroll
        for (int nf = 0; nf < 8; nf++) {
            const int col = col0 + wn + nf * 8 + 2 * t4;
            const float b0 = bias[col], b1 = bias[col + 1];
            const float v00 = acc[mi][nf][0] + b0, v01 = acc[mi][nf][1] + b1;
            const float v10 = acc[mi][nf][2] + b0, v11 = acc[mi][nf][3] + b1;
            if (OUT_HALF) {
                __half2* o = (__half2*)Cout;
                o[((size_t)row * GN + col) >> 1]       = __floats2half2_rn(v00, v01);
                o[((size_t)(row + 8) * GN + col) >> 1] = __floats2half2_rn(v10, v11);
            } else {
                float* o = (float*)Cout;
                *(float2*)(o + (size_t)row * GN + col)       = make_float2(v00, v01);
                *(float2*)(o + (size_t)(row + 8) * GN + col) = make_float2(v10, v11);
            }
        }
    }
}

// ---------------------------------------------------------------------------
// Flash attention, fp16 mma, register-resident P. (unchanged from R3)
// CTA = 128 queries x one (b,h), 4 warps x 32 q. 64-key tiles,
// K/V double-buffered via cp.async. 128 threads.
// ---------------------------------------------------------------------------
__global__ __launch_bounds__(128)
void attn_h_kernel(const __half* __restrict__ Q, const __half* __restrict__ K,
                   const __half* __restrict__ V, __half* __restrict__ O)
{
    extern __shared__ char smraw[];
    const int t    = threadIdx.x;
    const int lane = t & 31;
    const int warp = t >> 5;
    const int g    = lane >> 2;
    const int t4   = lane & 3;
    const int q0   = blockIdx.x * 128;
    const size_t base = (size_t)blockIdx.z * SEQ * GN + (size_t)blockIdx.y * HDIM;
    const uint32_t smb = smem_u32(smraw);

    const int lrow = t >> 3;
    const int lcb  = t & 7;

    {
        const __half* Qg = Q + base + (size_t)q0 * GN;
#pragma unroll
        for (int i = 0; i < 8; i++) {
            const int r = lrow + i * 16;
            cp16(smb + SWZ(r * 128 + lcb * 16), Qg + (size_t)r * GN + lcb * 8);
        }
    }
    auto load_kv = [&](int kt, int s) {
        const __half* Kg = K + base + (size_t)(kt * 64) * GN;
        const __half* Vg = V + base + (size_t)(kt * 64) * GN;
        const uint32_t ks = smb + 16384 + s * 16384;
        const uint32_t vs = ks + 8192;
#pragma unroll
        for (int i = 0; i < 4; i++) {
            const int r = lrow + i * 16;
            const uint32_t off = SWZ(r * 128 + lcb * 16);
            cp16(ks + off, Kg + (size_t)r * GN + lcb * 8);
            cp16(vs + off, Vg + (size_t)r * GN + lcb * 8);
        }
    };

    load_kv(0, 0);
    cp_commit();
    load_kv(1, 1);
    cp_commit();
    cp_wait<1>();
    __syncthreads();

    uint32_t qa[2][4][4];
#pragma unroll
    for (int mi = 0; mi < 2; mi++)
#pragma unroll
        for (int kf = 0; kf < 4; kf++) {
            const int r  = warp * 32 + mi * 16 + (lane & 7) + ((lane >> 3) & 1) * 8;
            const int cb = kf * 32 + ((lane >> 4) & 1) * 16;
            ldsm4(qa[mi][kf][0], qa[mi][kf][1], qa[mi][kf][2], qa[mi][kf][3],
                  smb + SWZ(r * 128 + cb));
        }

    float mrun[2][2], lrun[2][2];
    float o[2][8][4];
#pragma unroll
    for (int mi = 0; mi < 2; mi++) {
        mrun[mi][0] = mrun[mi][1] = -1e30f;
        lrun[mi][0] = lrun[mi][1] = 0.f;
#pragma unroll
        for (int nf = 0; nf < 8; nf++)
#pragma unroll
            for (int r = 0; r < 4; r++) o[mi][nf][r] = 0.f;
    }

    const float cexp = 0.125f * 1.44269504089f;
    const int NT = SEQ / 64;

    for (int kt = 0; kt < NT; kt++) {
        const uint32_t ks = smb + 16384 + (kt & 1) * 16384;
        const uint32_t vs = ks + 8192;

        float s_[2][8][4];
#pragma unroll
        for (int mi = 0; mi < 2; mi++)
#pragma unroll
            for (int nf = 0; nf < 8; nf++)
#pragma unroll
                for (int r = 0; r < 4; r++) s_[mi][nf][r] = 0.f;

#pragma unroll
        for (int kf = 0; kf < 4; kf++) {
#pragma unroll
            for (int np = 0; np < 4; np++) {
                const int r  = np * 16 + (lane & 7) + ((lane >> 4) & 1) * 8;
                const int cb = kf * 32 + ((lane >> 3) & 1) * 16;
                uint32_t b0, b1, b2, b3;
                ldsm4(b0, b1, b2, b3, ks + SWZ(r * 128 + cb));
#pragma unroll
                for (int mi = 0; mi < 2; mi++) {
                    mma_h(s_[mi][np * 2],     qa[mi][kf], b0, b1);
                    mma_h(s_[mi][np * 2 + 1], qa[mi][kf], b2, b3);
                }
            }
        }

        uint32_t pa[2][4][4];
#pragma unroll
        for (int mi = 0; mi < 2; mi++) {
            float mx0 = -1e30f, mx1 = -1e30f;
#pragma unroll
            for (int nf = 0; nf < 8; nf++) {
                mx0 = fmaxf(mx0, fmaxf(s_[mi][nf][0], s_[mi][nf][1]));
                mx1 = fmaxf(mx1, fmaxf(s_[mi][nf][2], s_[mi][nf][3]));
            }
            mx0 = fmaxf(mx0, __shfl_xor_sync(0xffffffffu, mx0, 1));
            mx0 = fmaxf(mx0, __shfl_xor_sync(0xffffffffu, mx0, 2));
            mx1 = fmaxf(mx1, __shfl_xor_sync(0xffffffffu, mx1, 1));
            mx1 = fmaxf(mx1, __shfl_xor_sync(0xffffffffu, mx1, 2));

            const float mn0 = fmaxf(mrun[mi][0], mx0);
            const float mn1 = fmaxf(mrun[mi][1], mx1);
            const float a0  = exp2f((mrun[mi][0] - mn0) * cexp);
            const float a1  = exp2f((mrun[mi][1] - mn1) * cexp);
            mrun[mi][0] = mn0; mrun[mi][1] = mn1;

            float rs0 = 0.f, rs1 = 0.f;
#pragma unroll
            for (int nf = 0; nf < 8; nf++) {
                const float p0 = exp2f((s_[mi][nf][0] - mn0) * cexp);
                const float p1 = exp2f((s_[mi][nf][1] - mn0) * cexp);
                const float p2 = exp2f((s_[mi][nf][2] - mn1) * cexp);
                const float p3 = exp2f((s_[mi][nf][3] - mn1) * cexp);
                rs0 += p0 + p1;
                rs1 += p2 + p3;
                const int kf = nf >> 1, hf = (nf & 1) * 2;
                pa[mi][kf][hf]     = packh2(p0, p1);
                pa[mi][kf][hf + 1] = packh2(p2, p3);
            }
            rs0 += __shfl_xor_sync(0xffffffffu, rs0, 1);
            rs0 += __shfl_xor_sync(0xffffffffu, rs0, 2);
            rs1 += __shfl_xor_sync(0xffffffffu, rs1, 1);
            rs1 += __shfl_xor_sync(0xffffffffu, rs1, 2);
            lrun[mi][0] = lrun[mi][0] * a0 + rs0;
            lrun[mi][1] = lrun[mi][1] * a1 + rs1;
#pragma unroll
            for (int nf = 0; nf < 8; nf++) {
                o[mi][nf][0] *= a0; o[mi][nf][1] *= a0;
                o[mi][nf][2] *= a1; o[mi][nf][3] *= a1;
            }
        }

#pragma unroll
        for (int kf = 0; kf < 4; kf++) {
#pragma unroll
            for (int np = 0; np < 4; np++) {
                const int r  = kf * 16 + (lane & 7) + ((lane >> 3) & 1) * 8;
                const int cb = np * 32 + ((lane >> 4) & 1) * 16;
                uint32_t b0, b1, b2, b3;
                ldsm4t(b0, b1, b2, b3, vs + SWZ(r * 128 + cb));
#pragma unroll
                for (int mi = 0; mi < 2; mi++) {
                    mma_h(o[mi][np * 2],     pa[mi][kf], b0, b1);
                    mma_h(o[mi][np * 2 + 1], pa[mi][kf], b2, b3);
                }
            }
        }

        __syncthreads();
        if (kt + 2 < NT) { load_kv(kt + 2, kt & 1); cp_commit(); }
        if (kt + 1 < NT) {
            if (kt + 2 < NT) cp_wait<1>(); else cp_wait<0>();
            __syncthreads();
        }
    }

#pragma unroll
    for (int mi = 0; mi < 2; mi++) {
        const float inv0 = 1.f / lrun[mi][0];
        const float inv1 = 1.f / lrun[mi][1];
        const int row = q0 + warp * 32 + mi * 16 + g;
#pragma unroll
        for (int nf = 0; nf < 8; nf++) {
            const int col = nf * 8 + 2 * t4;
            *(__half2*)(O + base + (size_t)row * GN + col) =
                __floats2half2_rn(o[mi][nf][0] * inv0, o[mi][nf][1] * inv0);
            *(__half2*)(O + base + (size_t)(row + 8) * GN + col) =
                __floats2half2_rn(o[mi][nf][2] * inv1, o[mi][nf][3] * inv1);
        }
    }
}

// ---------------------------------------------------------------------------
extern "C" void kernel_launch(void* const* d_in, const int* in_sizes, int n_in,
                              void* d_out, int out_size)
{
    const float* x  = (const float*)d_in[0];
    const float* Wq = (const float*)d_in[1];
    const float* bq = (const float*)d_in[2];
    const float* Wk = (const float*)d_in[3];
    const float* bk = (const float*)d_in[4];
    const float* Wv = (const float*)d_in[5];
    const float* bv = (const float*)d_in[6];
    const float* Wo = (const float*)d_in[7];
    const float* bo = (const float*)d_in[8];
    float* out = (float*)d_out;

    __half *xh, *wqh, *wkh, *wvh, *woh, *qh, *kh, *vh, *ch;
    cudaGetSymbolAddress((void**)&xh,  g_Xh);
    cudaGetSymbolAddress((void**)&wqh, g_Wqh);
    cudaGetSymbolAddress((void**)&wkh, g_Wkh);
    cudaGetSymbolAddress((void**)&wvh, g_Wvh);
    cudaGetSymbolAddress((void**)&woh, g_Woh);
    cudaGetSymbolAddress((void**)&qh,  g_Qh);
    cudaGetSymbolAddress((void**)&kh,  g_Kh);
    cudaGetSymbolAddress((void**)&vh,  g_Vh);
    cudaGetSymbolAddress((void**)&ch,  g_Ch);

    {
        const int nx4 = GM * GK / 4;
        f2h_kernel<<<(nx4 + 255) / 256, 256>>>(x, xh, nx4);
        const int nw4 = GN * GK / 4;
        f2h_kernel<<<(nw4 + 255) / 256, 256>>>(Wq, wqh, nw4);
        f2h_kernel<<<(nw4 + 255) / 256, 256>>>(Wk, wkh, nw4);
        f2h_kernel<<<(nw4 + 255) / 256, 256>>>(Wv, wvh, nw4);
        f2h_kernel<<<(nw4 + 255) / 256, 256>>>(Wo, woh, nw4);
    }

    const int gsm = 3 * STG_SZ;   // 98304
    cudaFuncSetAttribute(gemm_h_kernel<1>,
                         cudaFuncAttributeMaxDynamicSharedMemorySize, gsm);
    cudaFuncSetAttribute(gemm_h_kernel<0>,
                         cudaFuncAttributeMaxDynamicSharedMemorySize, gsm);
    dim3 ggrid(GN / 128, GM / 128);

    gemm_h_kernel<1><<<ggrid, 128, gsm>>>(xh, wqh, bq, qh);
    gemm_h_kernel<1><<<ggrid, 128, gsm>>>(xh, wkh, bk, kh);
    gemm_h_kernel<1><<<ggrid, 128, gsm>>>(xh, wvh, bv, vh);

    const int asm_ = 49152;
    cudaFuncSetAttribute(attn_h_kernel,
                         cudaFuncAttributeMaxDynamicSharedMemorySize, asm_);
    dim3 agrid(SEQ / 128, NHEAD, BATCH);
    attn_h_kernel<<<agrid, 128, asm_>>>(qh, kh, vh, ch);

    gemm_h_kernel<0><<<ggrid, 128, gsm>>>(ch, woh, bo, out);
}